// round 10
// baseline (speedup 1.0000x reference)
#include <cuda_runtime.h>
#include <cuda_bf16.h>

// Problem constants: x shape (64, 20, 64, 32, 32) fp32
// B=64, CHI=20, D = 64*32*32 = 65536
#define B_   64
#define CHI_ 20
#define D_   65536

// Scratch (no cudaMalloc allowed) — scores and softmax weights
__device__ float g_scores[B_ * CHI_];
__device__ float g_alpha[B_ * CHI_];

// ---------------------------------------------------------------------------
// Kernel 1: scores[b,c] = (1/CHI) * dot(x[b,c,:], x[b,CHI-1,:])
// One block per (b, c). Coalesced float4 reads; last-row re-reads hit L2.
// ---------------------------------------------------------------------------
__global__ __launch_bounds__(256)
void scores_kernel(const float* __restrict__ x) {
    const int bc = blockIdx.x;
    const int b  = bc / CHI_;
    const int c  = bc % CHI_;

    const float4* __restrict__ frow =
        reinterpret_cast<const float4*>(x + (size_t)b * CHI_ * D_ + (size_t)c * D_);
    const float4* __restrict__ lrow =
        reinterpret_cast<const float4*>(x + (size_t)b * CHI_ * D_ + (size_t)(CHI_ - 1) * D_);

    float acc = 0.0f;
    // D/4 = 16384 float4 elements, 256 threads -> 64 iterations/thread.
    // Unroll 4 to keep >=8 LDGs in flight per thread (MLP for DRAM latency).
    #pragma unroll 4
    for (int i = threadIdx.x; i < D_ / 4; i += 256) {
        float4 f = frow[i];
        float4 l = lrow[i];
        acc += f.x * l.x + f.y * l.y + f.z * l.z + f.w * l.w;
    }

    // Block reduction: warp shuffle then shared.
    #pragma unroll
    for (int off = 16; off > 0; off >>= 1)
        acc += __shfl_down_sync(0xFFFFFFFFu, acc, off);

    __shared__ float warp_sums[8];
    const int lane = threadIdx.x & 31;
    const int wid  = threadIdx.x >> 5;
    if (lane == 0) warp_sums[wid] = acc;
    __syncthreads();

    if (wid == 0) {
        float v = (lane < 8) ? warp_sums[lane] : 0.0f;
        #pragma unroll
        for (int off = 4; off > 0; off >>= 1)
            v += __shfl_down_sync(0xFFFFFFFFu, v, off);
        if (lane == 0)
            g_scores[bc] = v * (1.0f / (float)CHI_);
    }
}

// ---------------------------------------------------------------------------
// Kernel 2: alpha[b,:] = softmax(scores[b,:]).  One thread per batch.
// ---------------------------------------------------------------------------
__global__ void alpha_kernel() {
    const int b = threadIdx.x;
    if (b >= B_) return;

    float s[CHI_];
    float m = -1e30f;
    #pragma unroll
    for (int c = 0; c < CHI_; c++) {
        s[c] = g_scores[b * CHI_ + c];
        m = fmaxf(m, s[c]);
    }
    float z = 0.0f;
    #pragma unroll
    for (int c = 0; c < CHI_; c++) {
        s[c] = __expf(s[c] - m);
        z += s[c];
    }
    const float inv = 1.0f / z;
    #pragma unroll
    for (int c = 0; c < CHI_; c++)
        g_alpha[b * CHI_ + c] = s[c] * inv;
}

// ---------------------------------------------------------------------------
// Kernel 3: out[b,d] = sum_c x_flat[b*CHI*D + d*CHI + c] * alpha[b,c]
// NOTE the reshape aliasing: the second einsum views the SAME flat buffer as
// (B, D, chi), so element (b,d,c) sits at flat offset d*CHI + c. Since
// CHI=20, the 20-float group starts at byte offset 80*d -> 16B aligned ->
// exactly 5 float4 loads per output, contiguous across the warp.
// ---------------------------------------------------------------------------
__global__ __launch_bounds__(256)
void out_kernel(const float* __restrict__ x, float* __restrict__ out) {
    __shared__ float alpha_s[CHI_];
    const int b = blockIdx.y;
    if (threadIdx.x < CHI_)
        alpha_s[threadIdx.x] = g_alpha[b * CHI_ + threadIdx.x];
    __syncthreads();

    const int d = blockIdx.x * 256 + threadIdx.x;   // gridDim.x = D/256

    const float4* __restrict__ p =
        reinterpret_cast<const float4*>(x + (size_t)b * CHI_ * D_ + (size_t)d * CHI_);

    float acc = 0.0f;
    #pragma unroll
    for (int j = 0; j < 5; j++) {
        float4 v = p[j];
        acc += v.x * alpha_s[j * 4 + 0];
        acc += v.y * alpha_s[j * 4 + 1];
        acc += v.z * alpha_s[j * 4 + 2];
        acc += v.w * alpha_s[j * 4 + 3];
    }
    out[(size_t)b * D_ + d] = acc;
}

// ---------------------------------------------------------------------------
extern "C" void kernel_launch(void* const* d_in, const int* in_sizes, int n_in,
                              void* d_out, int out_size) {
    const float* x   = (const float*)d_in[0];
    float*       out = (float*)d_out;

    // 1) scores: one block per (b,c)
    scores_kernel<<<B_ * CHI_, 256>>>(x);

    // 2) softmax over chi per batch
    alpha_kernel<<<1, B_>>>();

    // 3) weighted sum over the (B, D, chi) view
    dim3 grid(D_ / 256, B_);
    out_kernel<<<grid, 256>>>(x, out);
}